// round 15
// baseline (speedup 1.0000x reference)
#include <cuda_runtime.h>
#include <cstdint>
#include <math.h>

#define D_DIM   2048
#define E_DIM   64
#define TOPK    2
#define M_TILE  128
#define THREADS 256
#define BK      32                    /* k per half per chunk */
#define NCH     32
#define TPAD    1040                  /* 16kp*64B + 16B pad: ≡4 words mod 32 */
#define XH_B    (16 * TPAD)           /* 16640 per x half */
#define WOFF    (2 * XH_B)            /* 33280 */
#define WH_B    (8 * TPAD)            /* 8320 per W half */
#define STAGE_B (2 * XH_B + 2 * WH_B) /* 49920 */
#define NSTAGE  4
#define SMEM_TOTAL (NSTAGE * STAGE_B) /* 199680 */
#define LG_STRIDE 65
#define LGB_OFF (M_TILE * LG_STRIDE * 4)   /* 33280 */
#define TAU     1e-5f

__device__ __forceinline__ uint32_t smem_u32(const void* p) {
    uint32_t a;
    asm("{ .reg .u64 t; cvta.to.shared.u64 t, %1; cvt.u32.u64 %0, t; }" : "=r"(a) : "l"(p));
    return a;
}
#define CP8(d, s) asm volatile("cp.async.ca.shared.global [%0], [%1], 8;" \
    :: "r"(d), "l"(s) : "memory")
#define CP_COMMIT() asm volatile("cp.async.commit_group;" ::: "memory")
#define CP_WAIT2()  asm volatile("cp.async.wait_group 2;" ::: "memory")

extern __shared__ char smem[];

__global__ __launch_bounds__(THREADS, 1) void router_ffma2_kernel(
    const float* __restrict__ x, const float* __restrict__ W,
    float* __restrict__ out, int T)
{
    const uint32_t sb = smem_u32(smem);
    const int tid  = threadIdx.x;
    const int lane = tid & 31;
    const int wid  = tid >> 5;
    const int t0   = blockIdx.x * M_TILE;
    const int tg   = lane >> 3;       // token group 0..3 (tokens tg + 4i)
    const int eg   = lane & 7;        // expert group 0..7 (experts eg + 8j)
    const int mg   = wid & 3;         // m-group: tokens mg*32 ..
    const int kh   = wid >> 2;        // k-half 0/1

    const int kpl   = tid & 15;       // loader lane k-pair
    const int rbase = tid >> 4;       // loader row base 0..15

    unsigned long long acc[8][8];
#pragma unroll
    for (int i = 0; i < 8; ++i)
#pragma unroll
        for (int j = 0; j < 8; ++j) acc[i][j] = 0ull;

#define ISSUE(kc)                                                             \
    {  const uint32_t stg = sb + ((kc) & 3) * STAGE_B;                        \
       _Pragma("unroll")                                                      \
       for (int h = 0; h < 2; ++h) {                                          \
           _Pragma("unroll")                                                  \
           for (int p = 0; p < 8; ++p) {                                      \
               int row = p * 16 + rbase;                                      \
               int mgl = row >> 5, r5 = row & 31;                             \
               int tgl = r5 & 3, ii = r5 >> 2;                                \
               uint32_t d = stg + (uint32_t)(h * XH_B + (mgl * 4 + tgl) * TPAD \
                          + kpl * 64 + ((ii ^ kpl) & 7) * 8);                 \
               const float* s = x + (size_t)(t0 + row) * D_DIM                \
                              + h * 1024 + (kc) * BK + kpl * 2;               \
               CP8(d, s);                                                     \
           }                                                                  \
           _Pragma("unroll")                                                  \
           for (int p = 0; p < 4; ++p) {                                      \
               int row = p * 16 + rbase;                                      \
               int egl = row & 7, jl = row >> 3;                              \
               uint32_t d = stg + (uint32_t)(WOFF + h * WH_B + egl * TPAD     \
                          + kpl * 64 + ((jl ^ kpl) & 7) * 8);                 \
               const float* s = W + (size_t)row * D_DIM                       \
                              + h * 1024 + (kc) * BK + kpl * 2;               \
               CP8(d, s);                                                     \
           } } }

#define COMPUTE(s)                                                            \
    {  const uint32_t stg = sb + (s) * STAGE_B;                               \
       const uint32_t ab = stg + (uint32_t)(kh * XH_B + (mg * 4 + tg) * TPAD); \
       const uint32_t bb = stg + (uint32_t)(WOFF + kh * WH_B + eg * TPAD);    \
       _Pragma("unroll")                                                      \
       for (int kp = 0; kp < 16; ++kp) {                                      \
           unsigned long long ar[8], br[8];                                   \
           _Pragma("unroll")                                                  \
           for (int q = 0; q < 4; ++q) {                                      \
               asm volatile("ld.shared.v2.u64 {%0,%1}, [%2];"                 \
                   : "=l"(ar[2*q]), "=l"(ar[2*q+1])                           \
                   : "r"(ab + (uint32_t)(kp * 64 + q * 16)));                 \
               asm volatile("ld.shared.v2.u64 {%0,%1}, [%2];"                 \
                   : "=l"(br[2*q]), "=l"(br[2*q+1])                           \
                   : "r"(bb + (uint32_t)(kp * 64 + q * 16)));                 \
           }                                                                  \
           _Pragma("unroll")                                                  \
           for (int i = 0; i < 8; ++i)                                        \
           _Pragma("unroll")                                                  \
           for (int j = 0; j < 8; ++j)                                        \
               asm("fma.rn.f32x2 %0, %1, %2, %0;"                             \
                   : "+l"(acc[i][j])                                          \
                   : "l"(ar[(i ^ kp) & 7]), "l"(br[(j ^ kp) & 7]));           \
       } }

    // -------- prologue --------
    ISSUE(0); CP_COMMIT();
    ISSUE(1); CP_COMMIT();
    ISSUE(2); CP_COMMIT();

    // -------- main loop: 4 stages, ONE barrier per chunk --------
    for (int kc = 0; kc < NCH; ++kc) {
        CP_WAIT2();
        __syncthreads();
        COMPUTE(kc & 3);
        if (kc + 3 < NCH) ISSUE(kc + 3);
        CP_COMMIT();
    }

    // -------- dump partial logits (per k-half); safe: stages 0-1 not live --
    float* lg = (float*)smem;
    float* lgh = (float*)(smem + kh * LGB_OFF);
#pragma unroll
    for (int i = 0; i < 8; ++i) {
        int trow = mg * 32 + tg + 4 * i;
#pragma unroll
        for (int j = 0; j < 8; ++j) {
            float lo, hi;
            asm("mov.b64 {%0,%1}, %2;" : "=f"(lo), "=f"(hi) : "l"(acc[i][j]));
            lgh[trow * LG_STRIDE + eg + 8 * j] = lo + hi;
        }
    }
    __syncthreads();

    // -------- per-token epilogue: threads 0..127 --------
    if (tid < M_TILE) {
        float lrow[E_DIM];
#pragma unroll 8
        for (int e = 0; e < E_DIM; ++e)
            lrow[e] = lg[tid * LG_STRIDE + e] + lg[(LGB_OFF / 4) + tid * LG_STRIDE + e];

        // top-4 scan ('>' keeps lower index first on ties, matching lax.top_k)
        float m0 = -INFINITY, m1 = -INFINITY, m2 = -INFINITY, m3 = -INFINITY;
        int i0 = 0, i1 = 0, i2 = 0, i3 = 0;
#pragma unroll 8
        for (int e = 0; e < E_DIM; ++e) {
            float v = lrow[e];
            if (v > m0)      { m3=m2;i3=i2; m2=m1;i2=i1; m1=m0;i1=i0; m0=v;i0=e; }
            else if (v > m1) { m3=m2;i3=i2; m2=m1;i2=i1; m1=v;i1=e; }
            else if (v > m2) { m3=m2;i3=i2; m2=v;i2=e; }
            else if (v > m3) { m3=v;i3=e; }
        }

        // fp64 fixup for near-ties (cheap insurance)
        bool flag = (m0 - m1 < TAU) || (m1 - m2 < TAU) || (m2 - m3 < TAU);
        unsigned bal = __ballot_sync(0xFFFFFFFFu, flag);
        while (bal) {
            int src = __ffs(bal) - 1;
            bal &= bal - 1;
            int tt = t0 + (wid << 5) + src;
            int e4[4];
            e4[0] = __shfl_sync(0xFFFFFFFFu, i0, src);
            e4[1] = __shfl_sync(0xFFFFFFFFu, i1, src);
            e4[2] = __shfl_sync(0xFFFFFFFFu, i2, src);
            e4[3] = __shfl_sync(0xFFFFFFFFu, i3, src);
            double s4[4] = {0.0, 0.0, 0.0, 0.0};
            const float* xrow2 = x + (size_t)tt * D_DIM;
            for (int k = lane; k < D_DIM; k += 32) {
                double xv = (double)xrow2[k];
#pragma unroll
                for (int j = 0; j < 4; ++j)
                    s4[j] += xv * (double)W[(size_t)e4[j] * D_DIM + k];
            }
#pragma unroll
            for (int off = 16; off > 0; off >>= 1)
#pragma unroll
                for (int j = 0; j < 4; ++j)
                    s4[j] += __shfl_xor_sync(0xFFFFFFFFu, s4[j], off);
            if (lane == src) {
                for (int a = 0; a < 3; ++a)
                    for (int b = 0; b < 3 - a; ++b)
                        if (s4[b + 1] > s4[b]) {
                            double td = s4[b]; s4[b] = s4[b + 1]; s4[b + 1] = td;
                            int ti = e4[b]; e4[b] = e4[b + 1]; e4[b + 1] = ti;
                        }
                i0 = e4[0];
                i1 = e4[1];
            }
        }

        // softmax + outputs
        float ssum = 0.f;
#pragma unroll 8
        for (int e = 0; e < E_DIM; ++e) ssum += expf(lrow[e] - m0);
        const float inv  = 1.0f / ssum;
        const float p1   = expf(lrow[i0] - m0) * inv;
        const float p2   = expf(lrow[i1] - m0) * inv;
        const float rinv = 1.0f / (p1 + p2);

        const int t = t0 + tid;
        const size_t TT = (size_t)T;
        float* mask_o = out + (size_t)t * E_DIM;
        float* idx_o  = out + TT * E_DIM + (size_t)t * TOPK;
        float* rp_o   = out + TT * (E_DIM + TOPK) + (size_t)t * E_DIM;
        float* p_o    = out + TT * (2 * E_DIM + TOPK) + (size_t)t * E_DIM;

        idx_o[0] = (float)i0;
        idx_o[1] = (float)i1;

#pragma unroll 4
        for (int e = 0; e < E_DIM; e += 4) {
            float4 pv, mv, rv;
            float p;
            p = expf(lrow[e + 0] - m0) * inv;
            mv.x = (e + 0 == i0 || e + 0 == i1) ? 1.0f : 0.0f; pv.x = p; rv.x = mv.x * p * rinv;
            p = expf(lrow[e + 1] - m0) * inv;
            mv.y = (e + 1 == i0 || e + 1 == i1) ? 1.0f : 0.0f; pv.y = p; rv.y = mv.y * p * rinv;
            p = expf(lrow[e + 2] - m0) * inv;
            mv.z = (e + 2 == i0 || e + 2 == i1) ? 1.0f : 0.0f; pv.z = p; rv.z = mv.z * p * rinv;
            p = expf(lrow[e + 3] - m0) * inv;
            mv.w = (e + 3 == i0 || e + 3 == i1) ? 1.0f : 0.0f; pv.w = p; rv.w = mv.w * p * rinv;

            *(float4*)(mask_o + e) = mv;
            *(float4*)(p_o    + e) = pv;
            *(float4*)(rp_o   + e) = rv;
        }
    }
}

extern "C" void kernel_launch(void* const* d_in, const int* in_sizes, int n_in,
                              void* d_out, int out_size)
{
    const float* x = (const float*)d_in[0];
    const float* W = (const float*)d_in[1];
    float* out = (float*)d_out;

    const int T = in_sizes[0] / D_DIM;      // 16384
    const int grid = T / M_TILE;            // 128

    cudaFuncSetAttribute(router_ffma2_kernel,
                         cudaFuncAttributeMaxDynamicSharedMemorySize, SMEM_TOTAL);
    router_ffma2_kernel<<<grid, THREADS, SMEM_TOTAL>>>(x, W, out, T);
}

// round 16
// speedup vs baseline: 1.1833x; 1.1833x over previous
#include <cuda_runtime.h>
#include <cstdint>
#include <math.h>

#define D_DIM   2048
#define E_DIM   64
#define TOPK    2
#define M_TILE  128
#define THREADS 256
#define BK      32                    /* k per half per chunk */
#define NCH     32                    /* (2048/2)/BK */
#define ROWB    144                   /* row stride bytes (36 words ≡ 4 mod 32) */
#define XH_B    (M_TILE * ROWB)       /* 18432 per x half */
#define WOFF    (2 * XH_B)            /* 36864 */
#define WH_B    (E_DIM * ROWB)        /* 9216 per W half */
#define STAGE_B (2 * XH_B + 2 * WH_B) /* 55296 */
#define NSTAGE  3
#define SMEM_TOTAL (NSTAGE * STAGE_B) /* 165888 */
#define LG_STRIDE 65
#define LGB_OFF (M_TILE * LG_STRIDE * 4)   /* 33280 */
#define TAU     1e-5f

__device__ __forceinline__ uint32_t smem_u32(const void* p) {
    uint32_t a;
    asm("{ .reg .u64 t; cvta.to.shared.u64 t, %1; cvt.u32.u64 %0, t; }" : "=r"(a) : "l"(p));
    return a;
}
#define CP16(d, s) asm volatile("cp.async.ca.shared.global [%0], [%1], 16;" \
    :: "r"(d), "l"(s) : "memory")
#define CP_COMMIT() asm volatile("cp.async.commit_group;" ::: "memory")
#define CP_WAIT1()  asm volatile("cp.async.wait_group 1;" ::: "memory")

extern __shared__ char smem[];

__global__ __launch_bounds__(THREADS, 1) void router_ffma2_kernel(
    const float* __restrict__ x, const float* __restrict__ W,
    float* __restrict__ out, int T)
{
    const uint32_t sb = smem_u32(smem);
    const int tid  = threadIdx.x;
    const int lane = tid & 31;
    const int wid  = tid >> 5;
    const int t0   = blockIdx.x * M_TILE;
    const int tg   = lane >> 3;       // token group 0..3 (tokens tg + 4i)
    const int eg   = lane & 7;        // expert group 0..7 (experts eg + 8j)
    const int mg   = wid & 3;         // m-group: tokens mg*32 ..
    const int kh   = wid >> 2;        // k-half 0/1

    const int xrow = tid >> 3, xcol = tid & 7;

    unsigned long long acc[8][8];
#pragma unroll
    for (int i = 0; i < 8; ++i)
#pragma unroll
        for (int j = 0; j < 8; ++j) acc[i][j] = 0ull;

#define ISSUE(kc)                                                             \
    {  const uint32_t stg = sb + ((kc) % NSTAGE) * STAGE_B;                   \
       _Pragma("unroll")                                                      \
       for (int h = 0; h < 2; ++h) {                                          \
           _Pragma("unroll")                                                  \
           for (int j = 0; j < 4; ++j) {                                      \
               int row = xrow + 32 * j;                                       \
               uint32_t d = stg + (uint32_t)(h * XH_B + row * ROWB + xcol * 16); \
               const float* s = x + (size_t)(t0 + row) * D_DIM                \
                              + h * 1024 + (kc) * BK + xcol * 4;              \
               CP16(d, s);                                                    \
           }                                                                  \
           _Pragma("unroll")                                                  \
           for (int j = 0; j < 2; ++j) {                                      \
               int idx = tid + 256 * j;                                       \
               int row = idx >> 3, col = idx & 7;                             \
               uint32_t d = stg + (uint32_t)(WOFF + h * WH_B + row * ROWB + col * 16); \
               const float* s = W + (size_t)row * D_DIM                       \
                              + h * 1024 + (kc) * BK + col * 4;               \
               CP16(d, s);                                                    \
           } } }

#define COMPUTE(s)                                                            \
    {  const uint32_t stg = sb + (s) * STAGE_B;                               \
       const uint32_t ab = stg + (uint32_t)(kh * XH_B + (mg * 32 + tg) * ROWB); \
       const uint32_t bb = stg + (uint32_t)(WOFF + kh * WH_B + eg * ROWB);    \
       _Pragma("unroll")                                                      \
       for (int kp = 0; kp < BK / 2; ++kp) {                                  \
           unsigned long long a[8], b[8];                                     \
           _Pragma("unroll")                                                  \
           for (int i = 0; i < 8; ++i)                                        \
               asm volatile("ld.shared.u64 %0, [%1];" : "=l"(a[i])            \
                   : "r"(ab + (uint32_t)(i * 4 * ROWB + kp * 8)));            \
           _Pragma("unroll")                                                  \
           for (int j = 0; j < 8; ++j)                                        \
               asm volatile("ld.shared.u64 %0, [%1];" : "=l"(b[j])            \
                   : "r"(bb + (uint32_t)(j * 8 * ROWB + kp * 8)));            \
           _Pragma("unroll")                                                  \
           for (int i = 0; i < 8; ++i)                                        \
           _Pragma("unroll")                                                  \
           for (int j = 0; j < 8; ++j)                                        \
               asm("fma.rn.f32x2 %0, %1, %2, %0;"                             \
                   : "+l"(acc[i][j]) : "l"(a[i]), "l"(b[j]));                 \
       } }

    // -------- prologue --------
    ISSUE(0); CP_COMMIT();
    ISSUE(1); CP_COMMIT();

    // -------- main loop: ONE barrier per chunk; loads issued before compute --
    for (int kc = 0; kc < NCH; ++kc) {
        CP_WAIT1();
        __syncthreads();
        if (kc + 2 < NCH) ISSUE(kc + 2);   // writes stage (kc-1)%3: safe post-barrier
        CP_COMMIT();
        COMPUTE(kc % NSTAGE);
    }
    __syncthreads();    // all compute done before logits overwrite stages 0/1

    // -------- dump partial logits (per k-half) --------
    float* lg = (float*)smem;           // lgA at 0, lgB at LGB_OFF
    float* lgh = (float*)(smem + kh * LGB_OFF);
#pragma unroll
    for (int i = 0; i < 8; ++i) {
        int trow = mg * 32 + tg + 4 * i;
#pragma unroll
        for (int j = 0; j < 8; ++j) {
            float lo, hi;
            asm("mov.b64 {%0,%1}, %2;" : "=f"(lo), "=f"(hi) : "l"(acc[i][j]));
            lgh[trow * LG_STRIDE + eg + 8 * j] = lo + hi;
        }
    }
    __syncthreads();

    // -------- per-token epilogue: threads 0..127 --------
    if (tid < M_TILE) {
        float lrow[E_DIM];
#pragma unroll 8
        for (int e = 0; e < E_DIM; ++e)
            lrow[e] = lg[tid * LG_STRIDE + e] + lg[(LGB_OFF / 4) + tid * LG_STRIDE + e];

        // top-4 scan ('>' keeps lower index first on ties, matching lax.top_k)
        float m0 = -INFINITY, m1 = -INFINITY, m2 = -INFINITY, m3 = -INFINITY;
        int i0 = 0, i1 = 0, i2 = 0, i3 = 0;
#pragma unroll 8
        for (int e = 0; e < E_DIM; ++e) {
            float v = lrow[e];
            if (v > m0)      { m3=m2;i3=i2; m2=m1;i2=i1; m1=m0;i1=i0; m0=v;i0=e; }
            else if (v > m1) { m3=m2;i3=i2; m2=m1;i2=i1; m1=v;i1=e; }
            else if (v > m2) { m3=m2;i3=i2; m2=v;i2=e; }
            else if (v > m3) { m3=v;i3=e; }
        }

        // fp64 fixup for near-ties (cheap insurance)
        bool flag = (m0 - m1 < TAU) || (m1 - m2 < TAU) || (m2 - m3 < TAU);
        unsigned bal = __ballot_sync(0xFFFFFFFFu, flag);
        while (bal) {
            int src = __ffs(bal) - 1;
            bal &= bal - 1;
            int tt = t0 + (wid << 5) + src;
            int e4[4];
            e4[0] = __shfl_sync(0xFFFFFFFFu, i0, src);
            e4[1] = __shfl_sync(0xFFFFFFFFu, i1, src);
            e4[2] = __shfl_sync(0xFFFFFFFFu, i2, src);
            e4[3] = __shfl_sync(0xFFFFFFFFu, i3, src);
            double s4[4] = {0.0, 0.0, 0.0, 0.0};
            const float* xrow2 = x + (size_t)tt * D_DIM;
            for (int k = lane; k < D_DIM; k += 32) {
                double xv = (double)xrow2[k];
#pragma unroll
                for (int j = 0; j < 4; ++j)
                    s4[j] += xv * (double)W[(size_t)e4[j] * D_DIM + k];
            }
#pragma unroll
            for (int off = 16; off > 0; off >>= 1)
#pragma unroll
                for (int j = 0; j < 4; ++j)
                    s4[j] += __shfl_xor_sync(0xFFFFFFFFu, s4[j], off);
            if (lane == src) {
                for (int a = 0; a < 3; ++a)
                    for (int b = 0; b < 3 - a; ++b)
                        if (s4[b + 1] > s4[b]) {
                            double td = s4[b]; s4[b] = s4[b + 1]; s4[b + 1] = td;
                            int ti = e4[b]; e4[b] = e4[b + 1]; e4[b + 1] = ti;
                        }
                i0 = e4[0];
                i1 = e4[1];
            }
        }

        // softmax + outputs
        float ssum = 0.f;
#pragma unroll 8
        for (int e = 0; e < E_DIM; ++e) ssum += expf(lrow[e] - m0);
        const float inv  = 1.0f / ssum;
        const float p1   = expf(lrow[i0] - m0) * inv;
        const float p2   = expf(lrow[i1] - m0) * inv;
        const float rinv = 1.0f / (p1 + p2);

        const int t = t0 + tid;
        const size_t TT = (size_t)T;
        float* mask_o = out + (size_t)t * E_DIM;
        float* idx_o  = out + TT * E_DIM + (size_t)t * TOPK;
        float* rp_o   = out + TT * (E_DIM + TOPK) + (size_t)t * E_DIM;
        float* p_o    = out + TT * (2 * E_DIM + TOPK) + (size_t)t * E_DIM;

        idx_o[0] = (float)i0;
        idx_o[1] = (float)i1;

#pragma unroll 4
        for (int e = 0; e < E_DIM; e += 4) {
            float4 pv, mv, rv;
            float p;
            p = expf(lrow[e + 0] - m0) * inv;
            mv.x = (e + 0 == i0 || e + 0 == i1) ? 1.0f : 0.0f; pv.x = p; rv.x = mv.x * p * rinv;
            p = expf(lrow[e + 1] - m0) * inv;
            mv.y = (e + 1 == i0 || e + 1 == i1) ? 1.0f : 0.0f; pv.y = p; rv.y = mv.y * p * rinv;
            p = expf(lrow[e + 2] - m0) * inv;
            mv.z = (e + 2 == i0 || e + 2 == i1) ? 1.0f : 0.0f; pv.z = p; rv.z = mv.z * p * rinv;
            p = expf(lrow[e + 3] - m0) * inv;
            mv.w = (e + 3 == i0 || e + 3 == i1) ? 1.0f : 0.0f; pv.w = p; rv.w = mv.w * p * rinv;

            *(float4*)(mask_o + e) = mv;
            *(float4*)(p_o    + e) = pv;
            *(float4*)(rp_o   + e) = rv;
        }
    }
}

extern "C" void kernel_launch(void* const* d_in, const int* in_sizes, int n_in,
                              void* d_out, int out_size)
{
    const float* x = (const float*)d_in[0];
    const float* W = (const float*)d_in[1];
    float* out = (float*)d_out;

    const int T = in_sizes[0] / D_DIM;      // 16384
    const int grid = T / M_TILE;            // 128

    cudaFuncSetAttribute(router_ffma2_kernel,
                         cudaFuncAttributeMaxDynamicSharedMemorySize, SMEM_TOTAL);
    router_ffma2_kernel<<<grid, THREADS, SMEM_TOTAL>>>(x, W, out, T);
}